// round 16
// baseline (speedup 1.0000x reference)
#include <cuda_runtime.h>
#include <cstddef>

#define B_   1024
#define T_   2048
#define CIN  9
#define C1   16
#define C2   32
#define RT   512
#define HID  128
#define OUTF 64

#define DINV2 0.7071067811865475f
#define DINV3 0.5773502691896258f

// ---------------- scratch ----------------
__device__ float g_h2[(size_t)B_ * RT * C2];     // conv2 pooled out, node-major, tf32-rounded

// ---------------- helpers ----------------
__device__ __forceinline__ unsigned f2tf32(float x) {
    unsigned u; asm("cvt.rna.tf32.f32 %0, %1;" : "=r"(u) : "f"(x)); return u;
}
__device__ __forceinline__ void mma_tf32(float c[4], unsigned a0, unsigned a1,
                                         unsigned a2, unsigned a3,
                                         unsigned b0, unsigned b1) {
    asm volatile("mma.sync.aligned.m16n8k8.row.col.f32.tf32.tf32.f32 "
                 "{%0,%1,%2,%3},{%4,%5,%6,%7},{%8,%9},{%0,%1,%2,%3};"
                 : "+f"(c[0]), "+f"(c[1]), "+f"(c[2]), "+f"(c[3])
                 : "r"(a0), "r"(a1), "r"(a2), "r"(a3), "r"(b0), "r"(b1));
}
__device__ __forceinline__ void cp_async16(unsigned dst, const void* src, int srcbytes) {
    asm volatile("cp.async.ca.shared.global [%0], [%1], 16, %2;"
                 :: "r"(dst), "l"(src), "r"(srcbytes));
}
__device__ __forceinline__ float stencil_apply(int t, float L, float S, float R) {
    float dt = (t == 0 || t == RT - 1) ? DINV2 : DINV3;
    float cL = (t > 0)      ? dt * ((t - 1 == 0)      ? DINV2 : DINV3) : 0.f;
    float cR = (t < RT - 1) ? dt * ((t + 1 == RT - 1) ? DINV2 : DINV3) : 0.f;
    return fmaf(cL, L, fmaf(dt * dt, S, cR * R));
}

// ============ fused conv1+conv2 (MMA): x -> h1 (smem) -> g_h2 (unchanged) ============
#define XSF_STRIDE 1044
#define H1_STRIDE  524
#define WS2_STRIDE 84
#define CONV_SMEM_BYTES ((10 * XSF_STRIDE + 16 * H1_STRIDE + 32 * WS2_STRIDE) * 4)

__global__ void __launch_bounds__(256) conv12_kernel(const float* __restrict__ x,
                                                     const float* __restrict__ w1,
                                                     const float* __restrict__ b1c,
                                                     const float* __restrict__ w2,
                                                     const float* __restrict__ b2c) {
    extern __shared__ float smc[];
    float* xs  = smc;
    float* h1s = smc + 10 * XSF_STRIDE;
    float* Ws  = h1s + 16 * H1_STRIDE;

    const int b = blockIdx.y, cx = blockIdx.x;
    const int tid = threadIdx.x;
    const int lane = tid & 31, warp = tid >> 5;
    const int gq = lane >> 2, tq = lane & 3;
    const int P0 = cx * 512;

    const float* xb = x + (size_t)b * CIN * T_;
    for (int i = tid; i < 10 * XSF_STRIDE; i += 256) {
        int r = i / XSF_STRIDE, j = i % XSF_STRIDE;
        int tg = cx * 1024 + j - 6;
        float v = (r < 9 && j < 1036 && (unsigned)tg < T_) ? xb[r * T_ + tg] : 0.f;
        xs[i] = __uint_as_float(f2tf32(v));
    }
    for (int i = tid; i < 32 * 80; i += 256) {
        int co = i / 80, k = i % 80;
        Ws[co * WS2_STRIDE + k] = __uint_as_float(f2tf32(w2[i]));
    }

    unsigned aw[6][4];
    int xoff0[6], xoff1[6];
#pragma unroll
    for (int ks = 0; ks < 6; ks++) {
        int k0 = ks * 8 + tq, k1 = k0 + 4;
        aw[ks][0] = (k0 < 45) ? f2tf32(w1[gq * 45 + k0])       : 0u;
        aw[ks][1] = (k0 < 45) ? f2tf32(w1[(gq + 8) * 45 + k0]) : 0u;
        aw[ks][2] = (k1 < 45) ? f2tf32(w1[gq * 45 + k1])       : 0u;
        aw[ks][3] = (k1 < 45) ? f2tf32(w1[(gq + 8) * 45 + k1]) : 0u;
        xoff0[ks] = (k0 / 5) * XSF_STRIDE + (k0 % 5);
        xoff1[ks] = (k1 / 5) * XSF_STRIDE + (k1 % 5);
    }
    const float c1b0 = b1c[gq], c1b1 = b1c[gq + 8];
    __syncthreads();

    for (int pi = warp; pi < 65; pi += 8) {
        const int ntA = pi * 2;
        float accA[4] = {0.f, 0.f, 0.f, 0.f}, accB[4] = {0.f, 0.f, 0.f, 0.f};
#pragma unroll
        for (int ks = 0; ks < 6; ks++) {
            int pA = ntA * 8 + gq;
            unsigned bA0 = __float_as_uint(xs[xoff0[ks] + pA]);
            unsigned bA1 = __float_as_uint(xs[xoff1[ks] + pA]);
            unsigned bB0 = __float_as_uint(xs[xoff0[ks] + pA + 8]);
            unsigned bB1 = __float_as_uint(xs[xoff1[ks] + pA + 8]);
            mma_tf32(accA, aw[ks][0], aw[ks][1], aw[ks][2], aw[ks][3], bA0, bA1);
            mma_tf32(accB, aw[ks][0], aw[ks][1], aw[ks][2], aw[ks][3], bB0, bB1);
        }
        int mA = ntA * 4 + tq, mB = mA + 4;
        if (mA < 516) {
            bool pv = (unsigned)(P0 - 2 + mA) < 1024;
            float v0 = pv ? fmaxf(fmaxf(accA[0], accA[1]) + c1b0, 0.f) : 0.f;
            float v1 = pv ? fmaxf(fmaxf(accA[2], accA[3]) + c1b1, 0.f) : 0.f;
            h1s[gq * H1_STRIDE + mA]       = __uint_as_float(f2tf32(v0));
            h1s[(gq + 8) * H1_STRIDE + mA] = __uint_as_float(f2tf32(v1));
        }
        if (mB < 516) {
            bool pv = (unsigned)(P0 - 2 + mB) < 1024;
            float v0 = pv ? fmaxf(fmaxf(accB[0], accB[1]) + c1b0, 0.f) : 0.f;
            float v1 = pv ? fmaxf(fmaxf(accB[2], accB[3]) + c1b1, 0.f) : 0.f;
            h1s[gq * H1_STRIDE + mB]       = __uint_as_float(f2tf32(v0));
            h1s[(gq + 8) * H1_STRIDE + mB] = __uint_as_float(f2tf32(v1));
        }
    }
    __syncthreads();

    int hoff0[10], hoff1[10];
#pragma unroll
    for (int ks = 0; ks < 10; ks++) {
        int k0 = ks * 8 + tq, k1 = k0 + 4;
        hoff0[ks] = (k0 / 5) * H1_STRIDE + (k0 % 5);
        hoff1[ks] = (k1 / 5) * H1_STRIDE + (k1 % 5);
    }
    const float bvA0 = b2c[gq],      bvA1 = b2c[gq + 8];
    const float bvB0 = b2c[16 + gq], bvB1 = b2c[24 + gq];

#pragma unroll
    for (int j = 0; j < 8; j += 2) {
        const int ntA = warp * 8 + j;
        float acc[2][2][4];
#pragma unroll
        for (int m = 0; m < 2; m++)
#pragma unroll
            for (int n = 0; n < 2; n++)
#pragma unroll
                for (int q = 0; q < 4; q++) acc[m][n][q] = 0.f;

#pragma unroll
        for (int ks = 0; ks < 10; ks++) {
            unsigned af[2][4];
#pragma unroll
            for (int m = 0; m < 2; m++) {
                int co0 = m * 16 + gq;
                af[m][0] = __float_as_uint(Ws[co0 * WS2_STRIDE + ks * 8 + tq]);
                af[m][1] = __float_as_uint(Ws[(co0 + 8) * WS2_STRIDE + ks * 8 + tq]);
                af[m][2] = __float_as_uint(Ws[co0 * WS2_STRIDE + ks * 8 + tq + 4]);
                af[m][3] = __float_as_uint(Ws[(co0 + 8) * WS2_STRIDE + ks * 8 + tq + 4]);
            }
            int pA = ntA * 8 + gq;
            unsigned bA0 = __float_as_uint(h1s[hoff0[ks] + pA]);
            unsigned bA1 = __float_as_uint(h1s[hoff1[ks] + pA]);
            unsigned bB0 = __float_as_uint(h1s[hoff0[ks] + pA + 8]);
            unsigned bB1 = __float_as_uint(h1s[hoff1[ks] + pA + 8]);
            mma_tf32(acc[0][0], af[0][0], af[0][1], af[0][2], af[0][3], bA0, bA1);
            mma_tf32(acc[1][0], af[1][0], af[1][1], af[1][2], af[1][3], bA0, bA1);
            mma_tf32(acc[0][1], af[0][0], af[0][1], af[0][2], af[0][3], bB0, bB1);
            mma_tf32(acc[1][1], af[1][0], af[1][1], af[1][2], af[1][3], bB0, bB1);
        }
        const size_t tb = (size_t)b * RT + cx * 256;
#pragma unroll
        for (int n = 0; n < 2; n++) {
            int t = (int)(ntA + n) * 4 + tq;
            float* g = g_h2 + (tb + t) * C2;
            g[gq]      = __uint_as_float(f2tf32(fmaxf(fmaxf(acc[0][n][0], acc[0][n][1]) + bvA0, 0.f)));
            g[gq + 8]  = __uint_as_float(f2tf32(fmaxf(fmaxf(acc[0][n][2], acc[0][n][3]) + bvA1, 0.f)));
            g[gq + 16] = __uint_as_float(f2tf32(fmaxf(fmaxf(acc[1][n][0], acc[1][n][1]) + bvB0, 0.f)));
            g[gq + 24] = __uint_as_float(f2tf32(fmaxf(fmaxf(acc[1][n][2], acc[1][n][3]) + bvB1, 0.f)));
        }
    }
}

// ======== fused GCN1 + GCN2 + mean + FC (paired float2 operand layouts) ========
// Pair index p = (k>>3)*4 + (k&3) packs (k, k+4) as one float2 -> fragment loads
// become single LDS.64. Layouts: W2p[m][p] (stride 66 f2), g1p[p][n] (stride 68 f2),
// in_p[r][pc] (stride 18 f2, in-place from the stencil phase).
#define SIN2  36
#define G1_REGION 9216          // floats reserved for g1p (8704 used) + fcw staging (8192)
#define GCN_SMEM_BYTES ((128 * 132 + G1_REGION + 72 * SIN2) * 4)   // 114816

__global__ void __launch_bounds__(256, 2) gcn_fused_kernel(
    const float* __restrict__ W1, const float* __restrict__ b1,
    const float* __restrict__ W2, const float* __restrict__ b2,
    const float* __restrict__ fcw, const float* __restrict__ fcb,
    float* __restrict__ out) {
    extern __shared__ float sm[];
    float* W2s  = sm;                        // float2[128][66]: W2p[m][p] = {W2[k0][m], W2[k0+4][m]}
    float* g1s  = sm + 128 * 132;            // float2[64][68]: g1p[p][n]; fcw staging at end
    float* in_s = g1s + G1_REGION;           // [72][SIN2]: raw X, then in-place paired S.X

    const int tid = threadIdx.x;
    const int b = blockIdx.x;
    const int warp = tid >> 5, lane = tid & 31;
    const int gq = lane >> 2, tq = lane & 3;
    const int fbase = warp * 16;
    const unsigned FULL = 0xffffffffu;
    const float C3 = DINV3 * DINV3;
    const unsigned in_sa = (unsigned)__cvta_generic_to_shared(in_s);

    // ---- prefetch chunk 0 ----
    {
#pragma unroll
        for (int it = 0; it < 3; it++) {
            int v = tid + it * 256;
            if (v < 576) {
                int r = v >> 3, c4 = v & 7;
                int t = -2 + r;
                bool valid = (unsigned)t < RT;
                int tc = valid ? t : 0;
                const float* src = g_h2 + ((size_t)b * RT + tc) * C2 + c4 * 4;
                cp_async16(in_sa + (unsigned)(r * SIN2 + c4 * 4) * 4, src, valid ? 16 : 0);
            }
        }
        asm volatile("cp.async.commit_group;");
    }

    // W2 paired staging (coalesced global reads, once per CTA)
    {
        float2* W2p = (float2*)W2s;
        for (int i = tid; i < 64 * HID; i += 256) {
            int m = i & 127, p = i >> 7;
            int k0 = ((p >> 2) << 3) | (p & 3);
            float2 v;
            v.x = __uint_as_float(f2tf32(W2[k0 * HID + m]));
            v.y = __uint_as_float(f2tf32(W2[(k0 + 4) * HID + m]));
            W2p[m * 66 + p] = v;
        }
    }
    unsigned aw1[4][4];
#pragma unroll
    for (int ks = 0; ks < 4; ks++) {
        int k0 = ks * 8 + tq;
        aw1[ks][0] = f2tf32(W1[k0 * HID + fbase + gq]);
        aw1[ks][1] = f2tf32(W1[k0 * HID + fbase + 8 + gq]);
        aw1[ks][2] = f2tf32(W1[(k0 + 4) * HID + fbase + gq]);
        aw1[ks][3] = f2tf32(W1[(k0 + 4) * HID + fbase + 8 + gq]);
    }
    const float b1v0 = b1[fbase + gq], b1v1 = b1[fbase + 8 + gq];
    const float b2v0 = b2[fbase + gq], b2v1 = b2[fbase + 8 + gq];
    float sum0 = 0.f, sum1 = 0.f;

    for (int chunk = 0; chunk < 8; chunk++) {
        const int t0 = chunk * 64;
        const bool bound = (chunk == 0) || (chunk == 7);
        asm volatile("cp.async.wait_group 0;");
        __syncthreads();                       // raw in_s ready; prev GEMM2 g1p reads done

        // ---- input-domain stencil, in-place, writes PAIRED layout: rows 1..70 ----
        {
            float tmp[9];
#pragma unroll
            for (int i = 0; i < 9; i++) {
                int e = tid + i * 256;
                tmp[i] = 0.f;
                if (e < 2240) {
                    int r = 1 + (e >> 5), c = e & 31;
                    float L = in_s[(r - 1) * SIN2 + c];
                    float S = in_s[r * SIN2 + c];
                    float R = in_s[(r + 1) * SIN2 + c];
                    tmp[i] = bound ? stencil_apply(t0 - 2 + r, L, S, R)
                                   : fmaf(C3, L, fmaf(C3, S, C3 * R));
                }
            }
            __syncthreads();                   // all raw reads before any paired write
#pragma unroll
            for (int i = 0; i < 9; i++) {
                int e = tid + i * 256;
                if (e < 2240) {
                    int r = 1 + (e >> 5), c = e & 31;
                    int pc = ((c >> 3) << 2) | (c & 3);
                    int slt = (c >> 2) & 1;
                    in_s[r * SIN2 + pc * 2 + slt] = __uint_as_float(f2tf32(tmp[i]));
                }
            }
            __syncthreads();                   // paired S.X ready for all warps
        }

        // ---- GEMM1: acc[nt][.] = ((S.X).W1), paired B loads (LDS.64) ----
        float acc[9][4];
#pragma unroll
        for (int nt = 0; nt < 9; nt++)
#pragma unroll
            for (int q = 0; q < 4; q++) acc[nt][q] = 0.f;
        {
            const float2* inp2 = (const float2*)in_s;
#pragma unroll
            for (int ks = 0; ks < 4; ks++)
#pragma unroll
                for (int nt = 0; nt < 9; nt++) {
                    float2 bb = inp2[(nt * 8 + gq) * 18 + ks * 4 + tq];
                    mma_tf32(acc[nt], aw1[ks][0], aw1[ks][1], aw1[ks][2], aw1[ks][3],
                             __float_as_uint(bb.x), __float_as_uint(bb.y));
                }
        }

        // ---- epilogue1: sg1 = S.relu(acc+b1) via shuffles -> g1p (paired slot write) ----
#pragma unroll
        for (int h = 0; h < 2; h++) {
            const int rowf = fbase + 8 * h + gq;
            const float bv = h ? b1v1 : b1v0;
            const int pr = ((rowf >> 3) << 2) | (rowf & 3);
            float* g1w = g1s + pr * 136 + ((rowf >> 2) & 1);
#pragma unroll
            for (int nt = 0; nt < 9; nt++) {
                float zE = acc[nt][2 * h], zO = acc[nt][2 * h + 1];
                float pO = __shfl_up_sync(FULL, zO, 1, 4);
                float nEv = __shfl_down_sync(FULL, zE, 1, 4);
                float pT = (nt > 0) ? __shfl_sync(FULL, acc[nt - 1][2 * h + 1], 3, 4) : 0.f;
                float nT = (nt < 8) ? __shfl_sync(FULL, acc[nt + 1][2 * h], 0, 4) : 0.f;
                float yLe = fmaxf(((tq == 0) ? pT : pO) + bv, 0.f);
                float yRo = fmaxf(((tq == 3) ? nT : nEv) + bv, 0.f);
                float yE = fmaxf(zE + bv, 0.f);
                float yO = fmaxf(zO + bv, 0.f);
                int ne = nt * 8 + 2 * tq, no = ne + 1;
                if (ne >= 2 && ne <= 65) {
                    float v = bound ? stencil_apply(t0 - 2 + ne, yLe, yE, yO)
                                    : fmaf(C3, yLe, fmaf(C3, yE, C3 * yO));
                    g1w[(ne - 2) * 2] = __uint_as_float(f2tf32(v));
                }
                if (no >= 2 && no <= 65) {
                    float v = bound ? stencil_apply(t0 - 2 + no, yE, yO, yRo)
                                    : fmaf(C3, yE, fmaf(C3, yO, C3 * yRo));
                    g1w[(no - 2) * 2] = __uint_as_float(f2tf32(v));
                }
            }
        }
        __syncthreads();                       // sg1 ready; in_s free

        // ---- prefetch next chunk (overlaps GEMM2) ----
        if (chunk < 7) {
            const int t0n = t0 + 64;
#pragma unroll
            for (int it = 0; it < 3; it++) {
                int v = tid + it * 256;
                if (v < 576) {
                    int r = v >> 3, c4 = v & 7;
                    int t = t0n - 2 + r;
                    bool valid = (unsigned)t < RT;
                    int tc = valid ? t : 0;
                    const float* src = g_h2 + ((size_t)b * RT + tc) * C2 + c4 * 4;
                    cp_async16(in_sa + (unsigned)(r * SIN2 + c4 * 4) * 4, src, valid ? 16 : 0);
                }
            }
            asm volatile("cp.async.commit_group;");
        }

        // ---- GEMM2: 8 n-tiles, fully paired operand loads (LDS.64) ----
        float acc2[8][4];
#pragma unroll
        for (int nt = 0; nt < 8; nt++)
#pragma unroll
            for (int q = 0; q < 4; q++) acc2[nt][q] = 0.f;
        {
            const float2* W2p = (const float2*)W2s;
            const float2* g1p = (const float2*)g1s;
#pragma unroll 8
            for (int ks = 0; ks < 16; ks++) {
                int p = ks * 4 + tq;
                float2 aL = W2p[(fbase + gq) * 66 + p];
                float2 aH = W2p[(fbase + 8 + gq) * 66 + p];
                unsigned a0 = __float_as_uint(aL.x), a1 = __float_as_uint(aH.x);
                unsigned a2 = __float_as_uint(aL.y), a3 = __float_as_uint(aH.y);
#pragma unroll
                for (int nt = 0; nt < 8; nt++) {
                    float2 bb = g1p[p * 68 + nt * 8 + gq];
                    mma_tf32(acc2[nt], a0, a1, a2, a3,
                             __float_as_uint(bb.x), __float_as_uint(bb.y));
                }
            }
        }

        // ---- epilogue2: relu + bias + time-mean accumulate (all cols valid) ----
        {
            float lsum0 = 0.f, lsum1 = 0.f;
#pragma unroll
            for (int nt = 0; nt < 8; nt++) {
                lsum0 += fmaxf(acc2[nt][0] + b2v0, 0.f) + fmaxf(acc2[nt][1] + b2v0, 0.f);
                lsum1 += fmaxf(acc2[nt][2] + b2v1, 0.f) + fmaxf(acc2[nt][3] + b2v1, 0.f);
            }
            sum0 += lsum0; sum1 += lsum1;
        }
    }

    // ---- epilogue: mean (in_s reused) + FC (fcw staged in g1s region) ----
    sum0 += __shfl_xor_sync(FULL, sum0, 1);
    sum0 += __shfl_xor_sync(FULL, sum0, 2);
    sum1 += __shfl_xor_sync(FULL, sum1, 1);
    sum1 += __shfl_xor_sync(FULL, sum1, 2);
    if (tq == 0) {
        in_s[fbase + gq]     = sum0 * (1.f / (float)RT);
        in_s[fbase + 8 + gq] = sum1 * (1.f / (float)RT);
    }
    __syncthreads();
    for (int i = tid; i < HID * OUTF; i += 256) g1s[i] = fcw[i];
    __syncthreads();
    if (tid < OUTF) {
        float acc = fcb[tid];
#pragma unroll 8
        for (int f = 0; f < HID; f++) acc = fmaf(in_s[f], g1s[f * OUTF + tid], acc);
        out[(size_t)b * OUTF + tid] = acc;
    }
}

// ---------------- launch ----------------
extern "C" void kernel_launch(void* const* d_in, const int* in_sizes, int n_in,
                              void* d_out, int out_size) {
    const float* x       = (const float*)d_in[0];
    const float* conv1_w = (const float*)d_in[1];
    const float* conv1_b = (const float*)d_in[2];
    const float* conv2_w = (const float*)d_in[3];
    const float* conv2_b = (const float*)d_in[4];
    const float* gcn1_w  = (const float*)d_in[5];
    const float* gcn1_b  = (const float*)d_in[6];
    const float* gcn2_w  = (const float*)d_in[7];
    const float* gcn2_b  = (const float*)d_in[8];
    const float* fc_w    = (const float*)d_in[9];
    const float* fc_b    = (const float*)d_in[10];
    float* out = (float*)d_out;

    static bool attr_set = false;
    if (!attr_set) {
        cudaFuncSetAttribute(conv12_kernel,
                             cudaFuncAttributeMaxDynamicSharedMemorySize, CONV_SMEM_BYTES);
        cudaFuncSetAttribute(gcn_fused_kernel,
                             cudaFuncAttributeMaxDynamicSharedMemorySize, GCN_SMEM_BYTES);
        attr_set = true;
    }

    conv12_kernel<<<dim3(2, B_), 256, CONV_SMEM_BYTES>>>(x, conv1_w, conv1_b,
                                                         conv2_w, conv2_b);
    gcn_fused_kernel<<<B_, 256, GCN_SMEM_BYTES>>>(gcn1_w, gcn1_b, gcn2_w, gcn2_b,
                                                  fc_w, fc_b, out);
}

// round 17
// speedup vs baseline: 1.1560x; 1.1560x over previous
#include <cuda_runtime.h>
#include <cstddef>

#define B_   1024
#define T_   2048
#define CIN  9
#define C1   16
#define C2   32
#define RT   512
#define HID  128
#define OUTF 64

#define DINV2 0.7071067811865475f
#define DINV3 0.5773502691896258f

// ---------------- scratch ----------------
__device__ float g_h2[(size_t)B_ * RT * C2];     // conv2 pooled out, node-major, tf32-rounded

// ---------------- helpers ----------------
__device__ __forceinline__ unsigned f2tf32(float x) {
    unsigned u; asm("cvt.rna.tf32.f32 %0, %1;" : "=r"(u) : "f"(x)); return u;
}
__device__ __forceinline__ void mma_tf32(float c[4], unsigned a0, unsigned a1,
                                         unsigned a2, unsigned a3,
                                         unsigned b0, unsigned b1) {
    asm volatile("mma.sync.aligned.m16n8k8.row.col.f32.tf32.tf32.f32 "
                 "{%0,%1,%2,%3},{%4,%5,%6,%7},{%8,%9},{%0,%1,%2,%3};"
                 : "+f"(c[0]), "+f"(c[1]), "+f"(c[2]), "+f"(c[3])
                 : "r"(a0), "r"(a1), "r"(a2), "r"(a3), "r"(b0), "r"(b1));
}
__device__ __forceinline__ void cp_async16(unsigned dst, const void* src, int srcbytes) {
    asm volatile("cp.async.ca.shared.global [%0], [%1], 16, %2;"
                 :: "r"(dst), "l"(src), "r"(srcbytes));
}
__device__ __forceinline__ float stencil_apply(int t, float L, float S, float R) {
    float dt = (t == 0 || t == RT - 1) ? DINV2 : DINV3;
    float cL = (t > 0)      ? dt * ((t - 1 == 0)      ? DINV2 : DINV3) : 0.f;
    float cR = (t < RT - 1) ? dt * ((t + 1 == RT - 1) ? DINV2 : DINV3) : 0.f;
    return fmaf(cL, L, fmaf(dt * dt, S, cR * R));
}

// ============ fused conv1+conv2 (MMA): x -> h1 (smem) -> g_h2 ============
// xs halo is 8 (float4-aligned staging); tap offsets carry the +2 shift, so all
// consumed values are bit-identical to the halo-6 version.
#define XSF_STRIDE 1044
#define H1_STRIDE  524
#define WS2_STRIDE 84
#define CONV_SMEM_BYTES ((10 * XSF_STRIDE + 16 * H1_STRIDE + 32 * WS2_STRIDE) * 4)

__global__ void __launch_bounds__(256) conv12_kernel(const float* __restrict__ x,
                                                     const float* __restrict__ w1,
                                                     const float* __restrict__ b1c,
                                                     const float* __restrict__ w2,
                                                     const float* __restrict__ b2c) {
    extern __shared__ float smc[];
    float* xs  = smc;                                   // [10][XSF_STRIDE], xs[j] = x[cx*1024 + j - 8]
    float* h1s = smc + 10 * XSF_STRIDE;                 // [16][H1_STRIDE]
    float* Ws  = h1s + 16 * H1_STRIDE;                  // [32][WS2_STRIDE]

    const int b = blockIdx.y, cx = blockIdx.x;          // cx in {0,1}
    const int tid = threadIdx.x;
    const int lane = tid & 31, warp = tid >> 5;
    const int gq = lane >> 2, tq = lane & 3;
    const int P0 = cx * 512;

    // ---- xs staging: float4 (rows of 1040 floats = 260 f4), tf32-rounded ----
    {
        const float4* xb4 = (const float4*)(x + (size_t)b * CIN * T_);
        for (int i = tid; i < 2600; i += 256) {
            int r = i / 260, q = i % 260;
            int g4 = cx * 256 - 2 + q;                  // f4 index within row
            float4 v = make_float4(0.f, 0.f, 0.f, 0.f);
            if (r < 9 && (unsigned)g4 < 512) v = xb4[r * 512 + g4];
            float4 o;
            o.x = __uint_as_float(f2tf32(v.x));
            o.y = __uint_as_float(f2tf32(v.y));
            o.z = __uint_as_float(f2tf32(v.z));
            o.w = __uint_as_float(f2tf32(v.w));
            *(float4*)(xs + r * XSF_STRIDE + q * 4) = o;
        }
        if (tid < 40) {                                 // zero pad tail j in [1040,1044)
            int r = tid >> 2, j = 1040 + (tid & 3);
            xs[r * XSF_STRIDE + j] = 0.f;
        }
    }
    // ---- Ws staging: float4 ----
    {
        const float4* w24 = (const float4*)w2;
        for (int i = tid; i < 640; i += 256) {
            int co = i / 20, qq = i % 20;
            float4 v = w24[i];
            float4 o;
            o.x = __uint_as_float(f2tf32(v.x));
            o.y = __uint_as_float(f2tf32(v.y));
            o.z = __uint_as_float(f2tf32(v.z));
            o.w = __uint_as_float(f2tf32(v.w));
            *(float4*)(Ws + co * WS2_STRIDE + qq * 4) = o;
        }
    }

    unsigned aw[6][4];
    int xoff0[6], xoff1[6];
#pragma unroll
    for (int ks = 0; ks < 6; ks++) {
        int k0 = ks * 8 + tq, k1 = k0 + 4;
        aw[ks][0] = (k0 < 45) ? f2tf32(w1[gq * 45 + k0])       : 0u;
        aw[ks][1] = (k0 < 45) ? f2tf32(w1[(gq + 8) * 45 + k0]) : 0u;
        aw[ks][2] = (k1 < 45) ? f2tf32(w1[gq * 45 + k1])       : 0u;
        aw[ks][3] = (k1 < 45) ? f2tf32(w1[(gq + 8) * 45 + k1]) : 0u;
        xoff0[ks] = (k0 / 5) * XSF_STRIDE + (k0 % 5) + 2;     // +2: halo-8 shift
        xoff1[ks] = (k1 / 5) * XSF_STRIDE + (k1 % 5) + 2;
    }
    const float c1b0 = b1c[gq], c1b1 = b1c[gq + 8];
    __syncthreads();

    // ---- stage 1: conv1 + pool -> h1s ----
    for (int pi = warp; pi < 65; pi += 8) {
        const int ntA = pi * 2;
        float accA[4] = {0.f, 0.f, 0.f, 0.f}, accB[4] = {0.f, 0.f, 0.f, 0.f};
#pragma unroll
        for (int ks = 0; ks < 6; ks++) {
            int pA = ntA * 8 + gq;
            unsigned bA0 = __float_as_uint(xs[xoff0[ks] + pA]);
            unsigned bA1 = __float_as_uint(xs[xoff1[ks] + pA]);
            unsigned bB0 = __float_as_uint(xs[xoff0[ks] + pA + 8]);
            unsigned bB1 = __float_as_uint(xs[xoff1[ks] + pA + 8]);
            mma_tf32(accA, aw[ks][0], aw[ks][1], aw[ks][2], aw[ks][3], bA0, bA1);
            mma_tf32(accB, aw[ks][0], aw[ks][1], aw[ks][2], aw[ks][3], bB0, bB1);
        }
        int mA = ntA * 4 + tq, mB = mA + 4;
        if (mA < 516) {
            bool pv = (unsigned)(P0 - 2 + mA) < 1024;
            float v0 = pv ? fmaxf(fmaxf(accA[0], accA[1]) + c1b0, 0.f) : 0.f;
            float v1 = pv ? fmaxf(fmaxf(accA[2], accA[3]) + c1b1, 0.f) : 0.f;
            h1s[gq * H1_STRIDE + mA]       = __uint_as_float(f2tf32(v0));
            h1s[(gq + 8) * H1_STRIDE + mA] = __uint_as_float(f2tf32(v1));
        }
        if (mB < 516) {
            bool pv = (unsigned)(P0 - 2 + mB) < 1024;
            float v0 = pv ? fmaxf(fmaxf(accB[0], accB[1]) + c1b0, 0.f) : 0.f;
            float v1 = pv ? fmaxf(fmaxf(accB[2], accB[3]) + c1b1, 0.f) : 0.f;
            h1s[gq * H1_STRIDE + mB]       = __uint_as_float(f2tf32(v0));
            h1s[(gq + 8) * H1_STRIDE + mB] = __uint_as_float(f2tf32(v1));
        }
    }
    __syncthreads();

    // ---- stage 2: conv2 + pool -> g_h2 ----
    int hoff0[10], hoff1[10];
#pragma unroll
    for (int ks = 0; ks < 10; ks++) {
        int k0 = ks * 8 + tq, k1 = k0 + 4;
        hoff0[ks] = (k0 / 5) * H1_STRIDE + (k0 % 5);
        hoff1[ks] = (k1 / 5) * H1_STRIDE + (k1 % 5);
    }
    const float bvA0 = b2c[gq],      bvA1 = b2c[gq + 8];
    const float bvB0 = b2c[16 + gq], bvB1 = b2c[24 + gq];

#pragma unroll
    for (int j = 0; j < 8; j += 2) {
        const int ntA = warp * 8 + j;
        float acc[2][2][4];
#pragma unroll
        for (int m = 0; m < 2; m++)
#pragma unroll
            for (int n = 0; n < 2; n++)
#pragma unroll
                for (int q = 0; q < 4; q++) acc[m][n][q] = 0.f;

#pragma unroll
        for (int ks = 0; ks < 10; ks++) {
            unsigned af[2][4];
#pragma unroll
            for (int m = 0; m < 2; m++) {
                int co0 = m * 16 + gq;
                af[m][0] = __float_as_uint(Ws[co0 * WS2_STRIDE + ks * 8 + tq]);
                af[m][1] = __float_as_uint(Ws[(co0 + 8) * WS2_STRIDE + ks * 8 + tq]);
                af[m][2] = __float_as_uint(Ws[co0 * WS2_STRIDE + ks * 8 + tq + 4]);
                af[m][3] = __float_as_uint(Ws[(co0 + 8) * WS2_STRIDE + ks * 8 + tq + 4]);
            }
            int pA = ntA * 8 + gq;
            unsigned bA0 = __float_as_uint(h1s[hoff0[ks] + pA]);
            unsigned bA1 = __float_as_uint(h1s[hoff1[ks] + pA]);
            unsigned bB0 = __float_as_uint(h1s[hoff0[ks] + pA + 8]);
            unsigned bB1 = __float_as_uint(h1s[hoff1[ks] + pA + 8]);
            mma_tf32(acc[0][0], af[0][0], af[0][1], af[0][2], af[0][3], bA0, bA1);
            mma_tf32(acc[1][0], af[1][0], af[1][1], af[1][2], af[1][3], bA0, bA1);
            mma_tf32(acc[0][1], af[0][0], af[0][1], af[0][2], af[0][3], bB0, bB1);
            mma_tf32(acc[1][1], af[1][0], af[1][1], af[1][2], af[1][3], bB0, bB1);
        }
        const size_t tb = (size_t)b * RT + cx * 256;
#pragma unroll
        for (int n = 0; n < 2; n++) {
            int t = (int)(ntA + n) * 4 + tq;
            float* g = g_h2 + (tb + t) * C2;
            g[gq]      = __uint_as_float(f2tf32(fmaxf(fmaxf(acc[0][n][0], acc[0][n][1]) + bvA0, 0.f)));
            g[gq + 8]  = __uint_as_float(f2tf32(fmaxf(fmaxf(acc[0][n][2], acc[0][n][3]) + bvA1, 0.f)));
            g[gq + 16] = __uint_as_float(f2tf32(fmaxf(fmaxf(acc[1][n][0], acc[1][n][1]) + bvB0, 0.f)));
            g[gq + 24] = __uint_as_float(f2tf32(fmaxf(fmaxf(acc[1][n][2], acc[1][n][3]) + bvB1, 0.f)));
        }
    }
}

// ======== fused GCN1 + GCN2 + mean + FC (R15 base; GEMM2 split m32 x n32) ========
// GEMM1: warp w -> feats w*16..+15, 9 n-tiles (unchanged).
// GEMM2: warp w -> feats (w&3)*32..+31, t-half (w>>2): n-tiles th*4..th*4+3.
//        Stencil2 is eliminated, so the column partition has zero redundancy.
#define SW2   132
#define SG1   72
#define SIN2  36
#define GCN_SMEM_BYTES ((128 * SW2 + 128 * SG1 + 72 * SIN2) * 4)   // 114816

__global__ void __launch_bounds__(256, 2) gcn_fused_kernel(
    const float* __restrict__ W1, const float* __restrict__ b1,
    const float* __restrict__ W2, const float* __restrict__ b2,
    const float* __restrict__ fcw, const float* __restrict__ fcb,
    float* __restrict__ out) {
    extern __shared__ float sm[];
    float* W2s  = sm;                        // [128][SW2]  W2^T
    float* g1s  = sm + 128 * SW2;            // [128 feats][SG1]; fcw staging at end
    float* in_s = g1s + 128 * SG1;           // [72][SIN2]; raw X then in-place S.X; mean buffer

    const int tid = threadIdx.x;
    const int b = blockIdx.x;
    const int warp = tid >> 5, lane = tid & 31;
    const int gq = lane >> 2, tq = lane & 3;
    const int fbase = warp * 16;             // GEMM1 m-base
    const int fg = warp & 3, th = warp >> 2; // GEMM2 roles
    const int fbase2 = fg * 32;
    const int ntg0 = th * 4;
    const unsigned FULL = 0xffffffffu;
    const float C3 = DINV3 * DINV3;
    const unsigned in_sa = (unsigned)__cvta_generic_to_shared(in_s);

    // ---- prefetch chunk 0 ----
    {
#pragma unroll
        for (int it = 0; it < 3; it++) {
            int v = tid + it * 256;
            if (v < 576) {
                int r = v >> 3, c4 = v & 7;
                int t = -2 + r;
                bool valid = (unsigned)t < RT;
                int tc = valid ? t : 0;
                const float* src = g_h2 + ((size_t)b * RT + tc) * C2 + c4 * 4;
                cp_async16(in_sa + (unsigned)(r * SIN2 + c4 * 4) * 4, src, valid ? 16 : 0);
            }
        }
        asm volatile("cp.async.commit_group;");
    }

    for (int i = tid; i < HID * HID; i += 256) {
        int k = i >> 7, m = i & 127;
        W2s[m * SW2 + k] = __uint_as_float(f2tf32(W2[i]));
    }
    unsigned aw1[4][4];
#pragma unroll
    for (int ks = 0; ks < 4; ks++) {
        int k0 = ks * 8 + tq;
        aw1[ks][0] = f2tf32(W1[k0 * HID + fbase + gq]);
        aw1[ks][1] = f2tf32(W1[k0 * HID + fbase + 8 + gq]);
        aw1[ks][2] = f2tf32(W1[(k0 + 4) * HID + fbase + gq]);
        aw1[ks][3] = f2tf32(W1[(k0 + 4) * HID + fbase + 8 + gq]);
    }
    const float b1v0 = b1[fbase + gq], b1v1 = b1[fbase + 8 + gq];
    float b2v2[2][2];
#pragma unroll
    for (int mt = 0; mt < 2; mt++) {
        b2v2[mt][0] = b2[fbase2 + mt * 16 + gq];
        b2v2[mt][1] = b2[fbase2 + mt * 16 + 8 + gq];
    }
    float s2[2][2] = {{0.f, 0.f}, {0.f, 0.f}};

    for (int chunk = 0; chunk < 8; chunk++) {
        const int t0 = chunk * 64;
        const bool bound = (chunk == 0) || (chunk == 7);
        asm volatile("cp.async.wait_group 0;");
        __syncthreads();                       // raw in_s ready; prev GEMM2 g1s reads done

        // ---- input-domain stencil, in-place: rows 1..70 ----
        {
            float tmp[9];
#pragma unroll
            for (int i = 0; i < 9; i++) {
                int e = tid + i * 256;
                tmp[i] = 0.f;
                if (e < 2240) {
                    int r = 1 + (e >> 5), c = e & 31;
                    float L = in_s[(r - 1) * SIN2 + c];
                    float S = in_s[r * SIN2 + c];
                    float R = in_s[(r + 1) * SIN2 + c];
                    tmp[i] = bound ? stencil_apply(t0 - 2 + r, L, S, R)
                                   : fmaf(C3, L, fmaf(C3, S, C3 * R));
                }
            }
            __syncthreads();
#pragma unroll
            for (int i = 0; i < 9; i++) {
                int e = tid + i * 256;
                if (e < 2240) {
                    int r = 1 + (e >> 5), c = e & 31;
                    in_s[r * SIN2 + c] = __uint_as_float(f2tf32(tmp[i]));
                }
            }
            __syncthreads();
        }

        // ---- GEMM1: acc[nt][.] = ((S.X).W1) at cols n <-> t = t0-2+n ----
        float acc[9][4];
#pragma unroll
        for (int nt = 0; nt < 9; nt++)
#pragma unroll
            for (int q = 0; q < 4; q++) acc[nt][q] = 0.f;
#pragma unroll
        for (int ks = 0; ks < 4; ks++)
#pragma unroll
            for (int nt = 0; nt < 9; nt++) {
                unsigned bb0 = __float_as_uint(in_s[(nt * 8 + gq) * SIN2 + ks * 8 + tq]);
                unsigned bb1 = __float_as_uint(in_s[(nt * 8 + gq) * SIN2 + ks * 8 + tq + 4]);
                mma_tf32(acc[nt], aw1[ks][0], aw1[ks][1], aw1[ks][2], aw1[ks][3], bb0, bb1);
            }

        // ---- epilogue1: sg1 = S.relu(acc+b1) via shuffles -> g1s cols n-2 ----
#pragma unroll
        for (int h = 0; h < 2; h++) {
            const int rowf = fbase + 8 * h + gq;
            const float bv = h ? b1v1 : b1v0;
#pragma unroll
            for (int nt = 0; nt < 9; nt++) {
                float zE = acc[nt][2 * h], zO = acc[nt][2 * h + 1];
                float pO = __shfl_up_sync(FULL, zO, 1, 4);
                float nEv = __shfl_down_sync(FULL, zE, 1, 4);
                float pT = (nt > 0) ? __shfl_sync(FULL, acc[nt - 1][2 * h + 1], 3, 4) : 0.f;
                float nT = (nt < 8) ? __shfl_sync(FULL, acc[nt + 1][2 * h], 0, 4) : 0.f;
                float yLe = fmaxf(((tq == 0) ? pT : pO) + bv, 0.f);
                float yRo = fmaxf(((tq == 3) ? nT : nEv) + bv, 0.f);
                float yE = fmaxf(zE + bv, 0.f);
                float yO = fmaxf(zO + bv, 0.f);
                int ne = nt * 8 + 2 * tq, no = ne + 1;
                if (ne >= 2 && ne <= 65) {
                    float v = bound ? stencil_apply(t0 - 2 + ne, yLe, yE, yO)
                                    : fmaf(C3, yLe, fmaf(C3, yE, C3 * yO));
                    g1s[rowf * SG1 + ne - 2] = __uint_as_float(f2tf32(v));
                }
                if (no >= 2 && no <= 65) {
                    float v = bound ? stencil_apply(t0 - 2 + no, yE, yO, yRo)
                                    : fmaf(C3, yE, fmaf(C3, yO, C3 * yRo));
                    g1s[rowf * SG1 + no - 2] = __uint_as_float(f2tf32(v));
                }
            }
        }
        __syncthreads();                       // sg1 ready; in_s free

        // ---- prefetch next chunk (overlaps GEMM2) ----
        if (chunk < 7) {
            const int t0n = t0 + 64;
#pragma unroll
            for (int it = 0; it < 3; it++) {
                int v = tid + it * 256;
                if (v < 576) {
                    int r = v >> 3, c4 = v & 7;
                    int t = t0n - 2 + r;
                    bool valid = (unsigned)t < RT;
                    int tc = valid ? t : 0;
                    const float* src = g_h2 + ((size_t)b * RT + tc) * C2 + c4 * 4;
                    cp_async16(in_sa + (unsigned)(r * SIN2 + c4 * 4) * 4, src, valid ? 16 : 0);
                }
            }
            asm volatile("cp.async.commit_group;");
        }

        // ---- GEMM2: m32 (feats fbase2..+31) x n32 (tiles ntg0..ntg0+3) ----
        float acc2[2][4][4];
#pragma unroll
        for (int mt = 0; mt < 2; mt++)
#pragma unroll
            for (int l = 0; l < 4; l++)
#pragma unroll
                for (int q = 0; q < 4; q++) acc2[mt][l][q] = 0.f;
#pragma unroll 8
        for (int ks = 0; ks < 16; ks++) {
            int k0 = ks * 8 + tq;
            unsigned af[2][4];
#pragma unroll
            for (int mt = 0; mt < 2; mt++) {
                int fb = fbase2 + mt * 16;
                af[mt][0] = __float_as_uint(W2s[(fb + gq) * SW2 + k0]);
                af[mt][1] = __float_as_uint(W2s[(fb + 8 + gq) * SW2 + k0]);
                af[mt][2] = __float_as_uint(W2s[(fb + gq) * SW2 + k0 + 4]);
                af[mt][3] = __float_as_uint(W2s[(fb + 8 + gq) * SW2 + k0 + 4]);
            }
#pragma unroll
            for (int l = 0; l < 4; l++) {
                int nb = (ntg0 + l) * 8 + gq;
                unsigned bb0 = __float_as_uint(g1s[k0 * SG1 + nb]);
                unsigned bb1 = __float_as_uint(g1s[(k0 + 4) * SG1 + nb]);
                mma_tf32(acc2[0][l], af[0][0], af[0][1], af[0][2], af[0][3], bb0, bb1);
                mma_tf32(acc2[1][l], af[1][0], af[1][1], af[1][2], af[1][3], bb0, bb1);
            }
        }

        // ---- epilogue2: relu + bias + time-mean accumulate (all owned cols valid) ----
#pragma unroll
        for (int mt = 0; mt < 2; mt++)
#pragma unroll
            for (int h = 0; h < 2; h++) {
                const float bv = b2v2[mt][h];
                float lsum = 0.f;
#pragma unroll
                for (int l = 0; l < 4; l++) {
                    lsum += fmaxf(acc2[mt][l][2 * h] + bv, 0.f)
                          + fmaxf(acc2[mt][l][2 * h + 1] + bv, 0.f);
                }
                s2[mt][h] += lsum;
            }
    }

    // ---- combine: tq-reduce, th halves via smem, then mean + FC ----
#pragma unroll
    for (int mt = 0; mt < 2; mt++)
#pragma unroll
        for (int h = 0; h < 2; h++) {
            s2[mt][h] += __shfl_xor_sync(FULL, s2[mt][h], 1);
            s2[mt][h] += __shfl_xor_sync(FULL, s2[mt][h], 2);
        }
    float* ms = in_s;
    if (th == 0 && tq == 0) {
#pragma unroll
        for (int mt = 0; mt < 2; mt++)
#pragma unroll
            for (int h = 0; h < 2; h++)
                ms[fbase2 + mt * 16 + 8 * h + gq] = s2[mt][h];
    }
    __syncthreads();
    if (th == 1 && tq == 0) {
#pragma unroll
        for (int mt = 0; mt < 2; mt++)
#pragma unroll
            for (int h = 0; h < 2; h++)
                ms[fbase2 + mt * 16 + 8 * h + gq] += s2[mt][h];
    }
    __syncthreads();
    if (tid < HID) ms[tid] *= (1.f / (float)RT);
    for (int i = tid; i < HID * OUTF; i += 256) g1s[i] = fcw[i];
    __syncthreads();
    if (tid < OUTF) {
        float acc = fcb[tid];
#pragma unroll 8
        for (int f = 0; f < HID; f++) acc = fmaf(ms[f], g1s[f * OUTF + tid], acc);
        out[(size_t)b * OUTF + tid] = acc;
    }
}

// ---------------- launch ----------------
extern "C" void kernel_launch(void* const* d_in, const int* in_sizes, int n_in,
                              void* d_out, int out_size) {
    const float* x       = (const float*)d_in[0];
    const float* conv1_w = (const float*)d_in[1];
    const float* conv1_b = (const float*)d_in[2];
    const float* conv2_w = (const float*)d_in[3];
    const float* conv2_b = (const float*)d_in[4];
    const float* gcn1_w  = (const float*)d_in[5];
    const float* gcn1_b  = (const float*)d_in[6];
    const float* gcn2_w  = (const float*)d_in[7];
    const float* gcn2_b  = (const float*)d_in[8];
    const float* fc_w    = (const float*)d_in[9];
    const float* fc_b    = (const float*)d_in[10];
    float* out = (float*)d_out;

    static bool attr_set = false;
    if (!attr_set) {
        cudaFuncSetAttribute(conv12_kernel,
                             cudaFuncAttributeMaxDynamicSharedMemorySize, CONV_SMEM_BYTES);
        cudaFuncSetAttribute(gcn_fused_kernel,
                             cudaFuncAttributeMaxDynamicSharedMemorySize, GCN_SMEM_BYTES);
        attr_set = true;
    }

    conv12_kernel<<<dim3(2, B_), 256, CONV_SMEM_BYTES>>>(x, conv1_w, conv1_b,
                                                         conv2_w, conv2_b);
    gcn_fused_kernel<<<B_, 256, GCN_SMEM_BYTES>>>(gcn1_w, gcn1_b, gcn2_w, gcn2_b,
                                                  fc_w, fc_b, out);
}